// round 7
// baseline (speedup 1.0000x reference)
#include <cuda_runtime.h>
#include <cstdint>

// CTC greedy decode:  probs [B, T=512, C=128] f32  ->  out [B, T]
// best[t] = argmax_c probs[b,t,c] (first-max tie-break, like jnp.argmax)
// valid[t] = best[t] != best[t-1] (prev=-1 at t=0)  &&  best[t] != C-1 (blank)
// out row  = table[best] for valid t (left-packed), tail = default_char.
//
// NOTE: output written as FLOAT32 values (e.g. 65.0f). Hypothesis from three
// rounds of rel_err == exactly 1.0: the harness compares d_out as float32,
// so int32 bit patterns read as denormals (~0) -> rel_err exactly 1.0.
//
// Inputs bound BY SIZE (robust to ordering + bytes-vs-elements units):
//   largest              -> probs  [B*T*C]
//   == 128 (or 512 B)    -> table  [C]
//   == 1   (or 4 B)      -> default_char scalar

#define CTC_T 512
#define CTC_C 128
#define CTC_BLANK (CTC_C - 1)
#define CTC_THREADS 512
#define CTC_WARPS (CTC_THREADS / 32)

template<bool VEC4>
__global__ __launch_bounds__(CTC_THREADS)
void ctc_decode_kernel(const float* __restrict__ probs,
                       const int* __restrict__ table,
                       const int* __restrict__ defc_ptr,
                       float* __restrict__ out,
                       long long n_probs_elems)
{
    __shared__ int s_best[CTC_T];
    __shared__ int s_wsum[CTC_WARPS];
    __shared__ float s_table[CTC_C];

    const int b    = blockIdx.x;
    const int tid  = threadIdx.x;
    const int lane = tid & 31;
    const int wid  = tid >> 5;

    // Bounds guard: never read past the probs buffer even if B over-estimated.
    if ((long long)(b + 1) * CTC_T * CTC_C > n_probs_elems) return;

    if (tid < CTC_C) s_table[tid] = (float)table[tid];

    const float* __restrict__ base = probs + (size_t)b * CTC_T * CTC_C;

    // ---- Phase 1: per-timestep argmax, one warp per timestep ----
    #pragma unroll 4
    for (int t = wid; t < CTC_T; t += CTC_WARPS) {
        float m;
        int   mi;
        if (VEC4) {
            const float4* p = reinterpret_cast<const float4*>(base + t * CTC_C) + lane;
            float4 v = __ldg(p);
            m  = v.x;  mi = lane * 4;
            if (v.y > m) { m = v.y; mi = lane * 4 + 1; }
            if (v.z > m) { m = v.z; mi = lane * 4 + 2; }
            if (v.w > m) { m = v.w; mi = lane * 4 + 3; }
        } else {
            // Coalesced scalar fallback; ascending indices per lane keep the
            // lowest index on ties (matching jnp.argmax).
            const float* row = base + t * CTC_C;
            m  = __ldg(row + lane);  mi = lane;
            #pragma unroll
            for (int k = 1; k < 4; ++k) {
                int   c = lane + k * 32;
                float v = __ldg(row + c);
                if (v > m) { m = v; mi = c; }
            }
        }
        // warp argmax, prefer lower index on exact tie
        #pragma unroll
        for (int off = 16; off > 0; off >>= 1) {
            float om  = __shfl_xor_sync(0xffffffffu, m,  off);
            int   omi = __shfl_xor_sync(0xffffffffu, mi, off);
            if (om > m || (om == m && omi < mi)) { m = om; mi = omi; }
        }
        if (lane == 0) s_best[t] = mi;
    }
    __syncthreads();

    // ---- Phase 2: valid flags + block scan (thread t owns timestep t) ----
    const int best  = s_best[tid];
    const int prevb = (tid == 0) ? -1 : s_best[tid - 1];
    const int valid = (best != prevb && best != CTC_BLANK) ? 1 : 0;

    int x = valid;
    #pragma unroll
    for (int off = 1; off < 32; off <<= 1) {
        int y = __shfl_up_sync(0xffffffffu, x, off);
        if (lane >= off) x += y;
    }
    if (lane == 31) s_wsum[wid] = x;
    __syncthreads();

    if (wid == 0) {
        int ws = (lane < CTC_WARPS) ? s_wsum[lane] : 0;
        #pragma unroll
        for (int off = 1; off < 32; off <<= 1) {
            int y = __shfl_up_sync(0xffffffffu, ws, off);
            if (lane >= off) ws += y;
        }
        if (lane < CTC_WARPS) s_wsum[lane] = ws;
    }
    __syncthreads();

    const int   incl  = x + (wid > 0 ? s_wsum[wid - 1] : 0);  // inclusive scan
    const int   count = s_wsum[CTC_WARPS - 1];                 // total valid
    const float defc  = defc_ptr ? (float)__ldg(defc_ptr) : 32.0f;

    float* __restrict__ orow = out + (size_t)b * CTC_T;
    if (valid)        orow[incl - 1] = s_table[best];  // packed [0, count)
    if (tid >= count) orow[tid]      = defc;           // tail [count, T), disjoint
}

extern "C" void kernel_launch(void* const* d_in, const int* in_sizes, int n_in,
                              void* d_out, int out_size)
{
    // --- bind inputs by size (elements or bytes auto-detected) ---
    int probs_i = 0;
    long long max_sz = -1;
    for (int i = 0; i < n_in; ++i)
        if ((long long)in_sizes[i] > max_sz) { max_sz = in_sizes[i]; probs_i = i; }

    int table_i = -1, defc_i = -1;
    int scale = 1;  // units-per-element of in_sizes (1 = elements, 4 = bytes)
    for (int i = 0; i < n_in; ++i) {
        if (i == probs_i) continue;
        const int s = in_sizes[i];
        if (s == CTC_C)                          { table_i = i; scale = 1; }
        else if (s == CTC_C * 4 && table_i < 0)  { table_i = i; scale = 4; }
        else if (s == 1 || s == 4)               { if (defc_i < 0) defc_i = i; }
    }
    if (table_i < 0) { table_i = (probs_i == 0 && n_in > 1) ? 1 : 0; scale = 1; }

    const float* probs = (const float*)d_in[probs_i];
    const int*   table = (const int*)d_in[table_i];
    const int*   defc  = (defc_i >= 0) ? (const int*)d_in[defc_i] : nullptr;
    float*       out   = (float*)d_out;

    const long long probs_elems = max_sz / scale;
    int B = (int)(probs_elems / ((long long)CTC_T * CTC_C));
    if (B <= 0) return;

    const bool aligned16 = ((uintptr_t)probs & 15u) == 0;
    if (aligned16)
        ctc_decode_kernel<true ><<<B, CTC_THREADS>>>(probs, table, defc, out, probs_elems);
    else
        ctc_decode_kernel<false><<<B, CTC_THREADS>>>(probs, table, defc, out, probs_elems);
}

// round 8
// speedup vs baseline: 1.2303x; 1.2303x over previous
#include <cuda_runtime.h>
#include <cstdint>

// CTC greedy decode:  probs [B, T=512, C=128] f32  ->  out [B, T] (float32 values)
// best[t] = argmax_c probs[b,t,c] (first-max tie-break, like jnp.argmax)
// valid[t] = best[t] != best[t-1] (prev=-1 at t=0)  &&  best[t] != C-1 (blank)
// out row  = table[best] for valid t (left-packed), tail = default_char.
//
// R7 confirmed: harness compares d_out as float32 -> write float values.
// This round: REDUX.SYNC warp argmax (replaces 5-round shuffle tree),
// 256-thread CTAs for a single full-chip wave, 2 timesteps/thread in phase 2.

#define CTC_T 512
#define CTC_C 128
#define CTC_BLANK (CTC_C - 1)
#define CTC_THREADS 256
#define CTC_WARPS (CTC_THREADS / 32)
#define CTC_TPW (CTC_T / CTC_WARPS)   // timesteps per warp = 64

// Order-preserving float->uint map (monotone for all finite floats).
__device__ __forceinline__ unsigned f2ord(float f) {
    unsigned u = __float_as_uint(f);
    return (u & 0x80000000u) ? ~u : (u | 0x80000000u);
}

template<bool VEC4>
__global__ __launch_bounds__(CTC_THREADS)
void ctc_decode_kernel(const float* __restrict__ probs,
                       const int* __restrict__ table,
                       const int* __restrict__ defc_ptr,
                       float* __restrict__ out,
                       long long n_probs_elems)
{
    __shared__ int   s_best[CTC_T];
    __shared__ int   s_wsum[CTC_WARPS];
    __shared__ float s_table[CTC_C];

    const int b    = blockIdx.x;
    const int tid  = threadIdx.x;
    const int lane = tid & 31;
    const int wid  = tid >> 5;

    // Bounds guard: never read past the probs buffer.
    if ((long long)(b + 1) * CTC_T * CTC_C > n_probs_elems) return;

    if (tid < CTC_C) s_table[tid] = (float)table[tid];

    const float* __restrict__ base = probs + (size_t)b * CTC_T * CTC_C;

    // ---- Phase 1: per-timestep argmax, one warp per timestep ----
    // Warp `wid` handles t = wid, wid+8, ... (consecutive warps -> contiguous
    // 4KB per pass). Lane-local 4-way argmax, then REDUX max/min across warp.
    #pragma unroll 4
    for (int t = wid; t < CTC_T; t += CTC_WARPS) {
        float m;
        int   mi;
        if (VEC4) {
            const float4* p = reinterpret_cast<const float4*>(base + t * CTC_C) + lane;
            float4 v = __ldg(p);
            m  = v.x;  mi = lane * 4;
            if (v.y > m) { m = v.y; mi = lane * 4 + 1; }
            if (v.z > m) { m = v.z; mi = lane * 4 + 2; }
            if (v.w > m) { m = v.w; mi = lane * 4 + 3; }
        } else {
            const float* row = base + t * CTC_C;
            m  = __ldg(row + lane);  mi = lane;
            #pragma unroll
            for (int k = 1; k < 4; ++k) {
                int   c = lane + k * 32;
                float v = __ldg(row + c);
                if (v > m) { m = v; mi = c; }
            }
        }
        // Warp argmax via REDUX: max of order-mapped value, then min index
        // among lanes holding the max (lowest-index tie-break, per jnp.argmax).
        const unsigned mo   = f2ord(m);
        const unsigned vmax = __reduce_max_sync(0xffffffffu, mo);
        const unsigned cand = (mo == vmax) ? (unsigned)mi : 0xffffffffu;
        const unsigned imin = __reduce_min_sync(0xffffffffu, cand);
        if (lane == 0) s_best[t] = (int)imin;
    }
    __syncthreads();

    // ---- Phase 2: valid flags + block scan; thread owns timesteps 2t, 2t+1 ----
    const int t0 = 2 * tid, t1 = 2 * tid + 1;
    const int b0 = s_best[t0];
    const int b1 = s_best[t1];
    const int p0 = (t0 == 0) ? -1 : s_best[t0 - 1];
    const int v0 = (b0 != p0 && b0 != CTC_BLANK) ? 1 : 0;
    const int v1 = (b1 != b0 && b1 != CTC_BLANK) ? 1 : 0;
    const int pair = v0 + v1;

    // inclusive scan of pair sums over 256 threads
    int x = pair;
    #pragma unroll
    for (int off = 1; off < 32; off <<= 1) {
        int y = __shfl_up_sync(0xffffffffu, x, off);
        if (lane >= off) x += y;
    }
    if (lane == 31) s_wsum[wid] = x;
    __syncthreads();

    if (wid == 0) {
        int ws = (lane < CTC_WARPS) ? s_wsum[lane] : 0;
        #pragma unroll
        for (int off = 1; off < CTC_WARPS; off <<= 1) {
            int y = __shfl_up_sync(0xffffffffu, ws, off);
            if (lane >= off) ws += y;
        }
        if (lane < CTC_WARPS) s_wsum[lane] = ws;
    }
    __syncthreads();

    const int incl_pair = x + (wid > 0 ? s_wsum[wid - 1] : 0); // inclusive over pairs
    const int excl      = incl_pair - pair;                     // exclusive before t0
    const int count     = s_wsum[CTC_WARPS - 1];                // total valid in row
    const float defc    = defc_ptr ? (float)__ldg(defc_ptr) : 32.0f;

    float* __restrict__ orow = out + (size_t)b * CTC_T;
    if (v0) orow[excl]           = s_table[b0];   // packed positions
    if (v1) orow[excl + v0]      = s_table[b1];
    if (t0 >= count) orow[t0]    = defc;          // tail padding (disjoint)
    if (t1 >= count) orow[t1]    = defc;
}

extern "C" void kernel_launch(void* const* d_in, const int* in_sizes, int n_in,
                              void* d_out, int out_size)
{
    // --- bind inputs by size (elements-vs-bytes auto-detected) ---
    int probs_i = 0;
    long long max_sz = -1;
    for (int i = 0; i < n_in; ++i)
        if ((long long)in_sizes[i] > max_sz) { max_sz = in_sizes[i]; probs_i = i; }

    int table_i = -1, defc_i = -1;
    int scale = 1;
    for (int i = 0; i < n_in; ++i) {
        if (i == probs_i) continue;
        const int s = in_sizes[i];
        if (s == CTC_C)                          { table_i = i; scale = 1; }
        else if (s == CTC_C * 4 && table_i < 0)  { table_i = i; scale = 4; }
        else if (s == 1 || s == 4)               { if (defc_i < 0) defc_i = i; }
    }
    if (table_i < 0) { table_i = (probs_i == 0 && n_in > 1) ? 1 : 0; scale = 1; }

    const float* probs = (const float*)d_in[probs_i];
    const int*   table = (const int*)d_in[table_i];
    const int*   defc  = (defc_i >= 0) ? (const int*)d_in[defc_i] : nullptr;
    float*       out   = (float*)d_out;

    const long long probs_elems = max_sz / scale;
    int B = (int)(probs_elems / ((long long)CTC_T * CTC_C));
    if (B <= 0) return;

    const bool aligned16 = ((uintptr_t)probs & 15u) == 0;
    if (aligned16)
        ctc_decode_kernel<true ><<<B, CTC_THREADS>>>(probs, table, defc, out, probs_elems);
    else
        ctc_decode_kernel<false><<<B, CTC_THREADS>>>(probs, table, defc, out, probs_elems);
}